// round 4
// baseline (speedup 1.0000x reference)
#include <cuda_runtime.h>
#include <cuda_bf16.h>
#include <cstdint>

#define N_NODES 100000
#define N_EDGES 1600000
#define D 64
#define H 128

// Scratch accumulator (allocation-free rule: __device__ global array)
__device__ float g_agg[N_NODES * D];
__device__ int g_ei_is64;   // 1 if edge_index is int64, 0 if int32

// ---------------------------------------------------------------------------
// helpers
// ---------------------------------------------------------------------------
__device__ __forceinline__ unsigned smem_u32(const void* p) {
    unsigned a;
    asm("{ .reg .u64 t; cvta.to.shared.u64 t, %1; cvt.u32.u64 %0, t; }"
        : "=r"(a) : "l"(p));
    return a;
}
__device__ __forceinline__ unsigned long long pack2(float x, float y) {
    unsigned long long u;
    asm("mov.b64 %0, {%1, %2};" : "=l"(u) : "f"(x), "f"(y));
    return u;
}
__device__ __forceinline__ float2 unpack2(unsigned long long u) {
    float2 f;
    asm("mov.b64 {%0, %1}, %2;" : "=f"(f.x), "=f"(f.y) : "l"(u));
    return f;
}
// packed fp32x2 FMA: d = a*b + d   (sm_103a FFMA2, PTX-only)
__device__ __forceinline__ void fma2(unsigned long long& d,
                                     unsigned long long a,
                                     unsigned long long b) {
    asm("fma.rn.f32x2 %0, %1, %2, %0;" : "+l"(d) : "l"(a), "l"(b));
}
__device__ __forceinline__ unsigned long long lds64(unsigned a) {
    unsigned long long v;
    asm volatile("ld.shared.b64 %0, [%1];" : "=l"(v) : "r"(a));
    return v;
}
__device__ __forceinline__ void lds64v2(unsigned long long& x, unsigned long long& y, unsigned a) {
    asm volatile("ld.shared.v2.b64 {%0, %1}, [%2];" : "=l"(x), "=l"(y) : "r"(a));
}
__device__ __forceinline__ void sts64v2(unsigned a, unsigned long long x, unsigned long long y) {
    asm volatile("st.shared.v2.b64 [%0], {%1, %2};" :: "r"(a), "l"(x), "l"(y));
}

// ---------------------------------------------------------------------------
// Kernel 0: detect edge_index dtype. If the buffer is int64 (little-endian,
// values < 2^31), every odd 32-bit word is 0. If int32, odd words are random
// node indices — P(all 64 sampled == 0) ~ 1e-320.
// ---------------------------------------------------------------------------
__global__ void detect_dtype_kernel(const int* __restrict__ ei32) {
    if (threadIdx.x == 0 && blockIdx.x == 0) {
        int all_zero = 1;
        for (int i = 0; i < 64; i++)
            if (ei32[2 * i + 1] != 0) { all_zero = 0; break; }
        g_ei_is64 = all_zero;
    }
}

// ---------------------------------------------------------------------------
// Kernel 1: agg = (1 + eps) * x   (eps = 0 -> plain copy)
// ---------------------------------------------------------------------------
__global__ void init_agg_kernel(const float4* __restrict__ x4) {
    int i = blockIdx.x * blockDim.x + threadIdx.x;
    if (i < N_NODES * D / 4) {
        reinterpret_cast<float4*>(g_agg)[i] = x4[i];
    }
}

// ---------------------------------------------------------------------------
// Kernel 2: scatter-add  agg[dst] += x[src]  over all edges.
// 16 threads per edge, each handling one float4 chunk (64 floats / edge).
// Vector reduction (red.global.add.v4.f32) -> 1 REDG.128 per thread.
// ---------------------------------------------------------------------------
__global__ void scatter_kernel(const float4* __restrict__ x4,
                               const int* __restrict__ ei32) {
    int t = blockIdx.x * blockDim.x + threadIdx.x;
    if (t >= N_EDGES * 16) return;
    int e = t >> 4;
    int c = t & 15;
    int src, dst;
    if (g_ei_is64) {
        src = __ldg(&ei32[2 * e]);
        dst = __ldg(&ei32[2 * N_EDGES + 2 * e]);
    } else {
        src = __ldg(&ei32[e]);
        dst = __ldg(&ei32[N_EDGES + e]);
    }
    float4 v = __ldg(&x4[(long long)src * 16 + c]);
    float* p = &g_agg[(long long)dst * 64 + c * 4];
    asm volatile("red.global.add.v4.f32 [%0], {%1, %2, %3, %4};"
                 :: "l"(p), "f"(v.x), "f"(v.y), "f"(v.z), "f"(v.w)
                 : "memory");
}

// ---------------------------------------------------------------------------
// Kernel 3: fused MLP  out = relu(agg @ W1 + b1) @ W2 + b2
// One warp processes 4 nodes at a time. Weights in smem as packed u64
// fp32-pairs; activations smem-duplicated {a,a} so every FMA uses FFMA2.
//
// Smem layout (dynamic, 96 KB):
//   sW1 : 64*64  u64  (W1[k][2p],W1[k][2p+1] pairs)   32 KB
//   sW2 : 128*32 u64                                   32 KB
//   buf : 8 warps * 512 u64 (activation broadcast)     32 KB
// ---------------------------------------------------------------------------
__global__ void mlp_kernel(const float* __restrict__ W1,
                           const float* __restrict__ b1,
                           const float* __restrict__ W2,
                           const float* __restrict__ b2,
                           float* __restrict__ out) {
    extern __shared__ unsigned long long sm[];
    unsigned long long* sW1 = sm;            // 4096
    unsigned long long* sW2 = sm + 4096;     // 4096
    unsigned long long* sBuf = sm + 8192;    // 4096

    const int tid = threadIdx.x;
    const int warp = tid >> 5;
    const int lane = tid & 31;

    // cooperative weight load: adjacent fp32 pairs == u64 reinterpret
    const unsigned long long* W1u = reinterpret_cast<const unsigned long long*>(W1);
    const unsigned long long* W2u = reinterpret_cast<const unsigned long long*>(W2);
    for (int i = tid; i < 64 * 64; i += blockDim.x) sW1[i] = W1u[i];
    for (int i = tid; i < 128 * 32; i += blockDim.x) sW2[i] = W2u[i];
    __syncthreads();

    const unsigned w1A = smem_u32(sW1);
    const unsigned w2A = smem_u32(sW2);
    const unsigned bufA = smem_u32(sBuf + warp * 512);

    // biases in regs: lane owns h outputs 4l..4l+3 and y outputs 2l..2l+1
    float4 bb1 = reinterpret_cast<const float4*>(b1)[lane];
    unsigned long long b1ab = pack2(bb1.x, bb1.y);
    unsigned long long b1cd = pack2(bb1.z, bb1.w);
    float2 bb2 = reinterpret_cast<const float2*>(b2)[lane];
    unsigned long long b2ab = pack2(bb2.x, bb2.y);

    const int warpsTotal = gridDim.x * (blockDim.x >> 5);
    const float2* aggv = reinterpret_cast<const float2*>(g_agg);

    for (int base = (blockIdx.x * (blockDim.x >> 5) + warp) * 4;
         base < N_NODES; base += warpsTotal * 4) {

        // ---- load activations, store duplicated {a,a} pairs ----
#pragma unroll
        for (int nb = 0; nb < 4; nb++) {
            int n = base + nb;
            float2 a = make_float2(0.f, 0.f);
            if (n < N_NODES) a = aggv[n * 32 + lane];
            sts64v2(bufA + (nb * 64 + 2 * lane) * 8,
                    pack2(a.x, a.x), pack2(a.y, a.y));
        }
        __syncwarp();

        // ---- layer 1: h = relu(a @ W1 + b1), lane -> outputs 4l..4l+3 ----
        unsigned long long acc0[4], acc1[4];
#pragma unroll
        for (int nb = 0; nb < 4; nb++) { acc0[nb] = b1ab; acc1[nb] = b1cd; }
#pragma unroll
        for (int k = 0; k < 64; k++) {
            unsigned long long w01, w23;
            lds64v2(w01, w23, w1A + (k * 64 + 2 * lane) * 8);
#pragma unroll
            for (int nb = 0; nb < 4; nb++) {
                unsigned long long a2 = lds64(bufA + (nb * 64 + k) * 8);
                fma2(acc0[nb], a2, w01);
                fma2(acc1[nb], a2, w23);
            }
        }
        __syncwarp();  // all buf reads done before overwrite

        // ---- relu + store duplicated h pairs ----
#pragma unroll
        for (int nb = 0; nb < 4; nb++) {
            float2 h01 = unpack2(acc0[nb]);
            float2 h23 = unpack2(acc1[nb]);
            float h0 = fmaxf(h01.x, 0.f), h1 = fmaxf(h01.y, 0.f);
            float h2 = fmaxf(h23.x, 0.f), h3 = fmaxf(h23.y, 0.f);
            sts64v2(bufA + (nb * 128 + 4 * lane) * 8, pack2(h0, h0), pack2(h1, h1));
            sts64v2(bufA + (nb * 128 + 4 * lane + 2) * 8, pack2(h2, h2), pack2(h3, h3));
        }
        __syncwarp();

        // ---- layer 2: y = h @ W2 + b2, lane -> outputs 2l..2l+1 ----
        unsigned long long acc2[4];
#pragma unroll
        for (int nb = 0; nb < 4; nb++) acc2[nb] = b2ab;
#pragma unroll
        for (int k = 0; k < 128; k++) {
            unsigned long long w = lds64(w2A + (k * 32 + lane) * 8);
#pragma unroll
            for (int nb = 0; nb < 4; nb++) {
                unsigned long long a2 = lds64(bufA + (nb * 128 + k) * 8);
                fma2(acc2[nb], a2, w);
            }
        }

        // ---- epilogue: coalesced float2 stores ----
#pragma unroll
        for (int nb = 0; nb < 4; nb++) {
            int n = base + nb;
            if (n < N_NODES) {
                float2 y = unpack2(acc2[nb]);
                reinterpret_cast<float2*>(out)[n * 32 + lane] = y;
            }
        }
        __syncwarp();  // buf reads done before next iteration's writes
    }
}

// ---------------------------------------------------------------------------
extern "C" void kernel_launch(void* const* d_in, const int* in_sizes, int n_in,
                              void* d_out, int out_size) {
    const float* x = (const float*)d_in[0];
    const int* ei32 = (const int*)d_in[1];
    const float* W1 = (const float*)d_in[2];
    const float* b1 = (const float*)d_in[3];
    const float* W2 = (const float*)d_in[4];
    const float* b2 = (const float*)d_in[5];
    float* out = (float*)d_out;

    // 0) detect edge_index dtype (int32 vs int64)
    detect_dtype_kernel<<<1, 32>>>(ei32);

    // 1) init agg = x
    {
        int n = N_NODES * D / 4;
        init_agg_kernel<<<(n + 255) / 256, 256>>>((const float4*)x);
    }
    // 2) scatter-add over edges
    {
        long long total = (long long)N_EDGES * 16;
        int blocks = (int)((total + 255) / 256);
        scatter_kernel<<<blocks, 256>>>((const float4*)x, ei32);
    }
    // 3) fused MLP
    {
        const int smemBytes = 96 * 1024;
        cudaFuncSetAttribute(mlp_kernel,
                             cudaFuncAttributeMaxDynamicSharedMemorySize,
                             smemBytes);
        mlp_kernel<<<296, 256, smemBytes>>>(W1, b1, W2, b2, out);
    }
}

// round 8
// speedup vs baseline: 1.2452x; 1.2452x over previous
#include <cuda_runtime.h>
#include <cuda_bf16.h>
#include <cstdint>

#define N_NODES 100000
#define N_EDGES 1600000
#define D 64
#define H 128

typedef unsigned long long u64;

// Scratch accumulator (allocation-free rule: __device__ global array)
__device__ float g_agg[N_NODES * D];
__device__ int g_ei_is64;   // 1 if edge_index is int64, 0 if int32

// ---------------------------------------------------------------------------
// helpers
// ---------------------------------------------------------------------------
__device__ __forceinline__ unsigned smem_u32(const void* p) {
    unsigned a;
    asm("{ .reg .u64 t; cvta.to.shared.u64 t, %1; cvt.u32.u64 %0, t; }"
        : "=r"(a) : "l"(p));
    return a;
}
__device__ __forceinline__ u64 pack2(float x, float y) {
    u64 u;
    asm("mov.b64 %0, {%1, %2};" : "=l"(u) : "f"(x), "f"(y));
    return u;
}
__device__ __forceinline__ float2 unpack2(u64 u) {
    float2 f;
    asm("mov.b64 {%0, %1}, %2;" : "=f"(f.x), "=f"(f.y) : "l"(u));
    return f;
}
// packed fp32x2 FMA: d = a*b + d   (sm_103a FFMA2, PTX-only)
__device__ __forceinline__ void fma2(u64& d, u64 a, u64 b) {
    asm("fma.rn.f32x2 %0, %1, %2, %0;" : "+l"(d) : "l"(a), "l"(b));
}
__device__ __forceinline__ u64 add2(u64 a, u64 b) {
    u64 r;
    asm("add.rn.f32x2 %0, %1, %2;" : "=l"(r) : "l"(a), "l"(b));
    return r;
}
__device__ __forceinline__ void lds64v2(u64& x, u64& y, unsigned a) {
    asm volatile("ld.shared.v2.b64 {%0, %1}, [%2];" : "=l"(x), "=l"(y) : "r"(a));
}
__device__ __forceinline__ void sts64(unsigned a, u64 v) {
    asm volatile("st.shared.b64 [%0], %1;" :: "r"(a), "l"(v));
}

// ---------------------------------------------------------------------------
// Kernel 0: detect edge_index dtype (int64 -> odd 32-bit words all zero).
// ---------------------------------------------------------------------------
__global__ void detect_dtype_kernel(const int* __restrict__ ei32) {
    if (threadIdx.x == 0 && blockIdx.x == 0) {
        int all_zero = 1;
        for (int i = 0; i < 64; i++)
            if (ei32[2 * i + 1] != 0) { all_zero = 0; break; }
        g_ei_is64 = all_zero;
    }
}

// ---------------------------------------------------------------------------
// Kernel 1: zero agg (the (1+eps)*x term is added inside the MLP instead)
// ---------------------------------------------------------------------------
__global__ void zero_agg_kernel() {
    int i = blockIdx.x * blockDim.x + threadIdx.x;
    if (i < N_NODES * D / 4)
        reinterpret_cast<float4*>(g_agg)[i] = make_float4(0.f, 0.f, 0.f, 0.f);
}

// ---------------------------------------------------------------------------
// Kernel 2: scatter-add  agg[dst] += x[src].  16 threads/edge, REDG.128.
// ---------------------------------------------------------------------------
__global__ void scatter_kernel(const float4* __restrict__ x4,
                               const int* __restrict__ ei32) {
    int t = blockIdx.x * blockDim.x + threadIdx.x;
    if (t >= N_EDGES * 16) return;
    int e = t >> 4;
    int c = t & 15;
    int src, dst;
    if (g_ei_is64) {
        src = __ldg(&ei32[2 * e]);
        dst = __ldg(&ei32[2 * N_EDGES + 2 * e]);
    } else {
        src = __ldg(&ei32[e]);
        dst = __ldg(&ei32[N_EDGES + e]);
    }
    float4 v = __ldg(&x4[(long long)src * 16 + c]);
    float* p = &g_agg[(long long)dst * 64 + c * 4];
    asm volatile("red.global.add.v4.f32 [%0], {%1, %2, %3, %4};"
                 :: "l"(p), "f"(v.x), "f"(v.y), "f"(v.z), "f"(v.w)
                 : "memory");
}

// ---------------------------------------------------------------------------
// Kernel 3: fused MLP, k-pair FFMA2 formulation, NB=8 nodes per warp-iter.
//
// acc{lo,hi} accumulates even-k / odd-k partial sums; h = lo + hi at the end.
// Activations: natural float2 (k-pair) layout, broadcast LDS.128 reads.
// Weights: pre-paired u64 {W[2k][o], W[2k+1][o]} in smem, lane-contiguous.
//
// Smem (u64 units):
//   sW1t: 32 kk * 128           = 4096 u64  (layout [kk][half][lane][2])
//   sW2t: 64 kk * 64            = 4096 u64  (layout [kk][o])
//   buf : 8 warps * 64 rows * 80B = 40960 B  (XOR-swizzled transpose buffer)
// Total = 106496 B.
// ---------------------------------------------------------------------------
__global__ void __launch_bounds__(256, 2)
mlp_kernel(const float* __restrict__ x,
           const float* __restrict__ W1,
           const float* __restrict__ b1,
           const float* __restrict__ W2,
           const float* __restrict__ b2,
           float* __restrict__ out) {
    extern __shared__ u64 sm[];
    u64* sW1 = sm;           // 4096
    u64* sW2 = sm + 4096;    // 4096
    char* sBuf = (char*)(sm + 8192);  // 40960 bytes

    const int tid = threadIdx.x;
    const int warp = tid >> 5;
    const int lane = tid & 31;

    // ---- weight prep ----
    // sW1t[kk][half][ln][j] = {W1[2kk][o], W1[2kk+1][o]}, o = 4*ln + 2*half + j
    for (int i = tid; i < 4096; i += 256) {
        int kk = i >> 7, r = i & 127;
        int half = r >> 6, t = r & 63;
        int ln = t >> 1, j = t & 1;
        int o = ln * 4 + half * 2 + j;
        sW1[i] = pack2(W1[(2 * kk) * H + o], W1[(2 * kk + 1) * H + o]);
    }
    // sW2t[kk][o] = {W2[2kk][o], W2[2kk+1][o]}
    for (int i = tid; i < 4096; i += 256) {
        int kk = i >> 6, o = i & 63;
        sW2[i] = pack2(W2[(2 * kk) * D + o], W2[(2 * kk + 1) * D + o]);
    }
    __syncthreads();

    const unsigned w1A = smem_u32(sW1);
    const unsigned w2A = smem_u32(sW2);
    const unsigned bufA = smem_u32(sBuf) + warp * 5120;  // 64 rows * 80B

    const float4 b1v = reinterpret_cast<const float4*>(b1)[lane];
    const float2 b2v = reinterpret_cast<const float2*>(b2)[lane];

    const u64* agg2 = reinterpret_cast<const u64*>(g_agg);
    const u64* x2 = reinterpret_cast<const u64*>(x);

    const int warpsTotal = gridDim.x * 8;

    for (int base = (blockIdx.x * 8 + warp) * 8; base < N_NODES;
         base += warpsTotal * 8) {

        // ---- load acts (agg + x), store transposed k-pair rows ----
        // row = lane (= kk), col = n ^ (lane>>2)  (conflict-free swizzle)
#pragma unroll
        for (int nb = 0; nb < 8; nb++) {
            u64 a = add2(agg2[(base + nb) * 32 + lane],
                         x2[(base + nb) * 32 + lane]);
            sts64(bufA + lane * 80 + (((nb ^ (lane >> 2)) & 7) << 3), a);
        }
        __syncwarp();

        // ---- layer 1: 128 outputs, lane owns o = 4l..4l+3 ----
        u64 ac0[8], ac1[8], ac2[8], ac3[8];
#pragma unroll
        for (int n = 0; n < 8; n++) {
            ac0[n] = pack2(b1v.x, 0.f);
            ac1[n] = pack2(b1v.y, 0.f);
            ac2[n] = pack2(b1v.z, 0.f);
            ac3[n] = pack2(b1v.w, 0.f);
        }
#pragma unroll
        for (int kk = 0; kk < 32; kk++) {
            const int s = (kk >> 2) & 7;
            u64 w0, w1, w2, w3;
            lds64v2(w0, w1, w1A + kk * 1024 + lane * 16);
            lds64v2(w2, w3, w1A + kk * 1024 + 512 + lane * 16);
            u64 t[8];
            unsigned rb = bufA + kk * 80;
            lds64v2(t[0], t[1], rb);
            lds64v2(t[2], t[3], rb + 16);
            lds64v2(t[4], t[5], rb + 32);
            lds64v2(t[6], t[7], rb + 48);
#pragma unroll
            for (int c = 0; c < 8; c++) {
                const int n = c ^ s;   // compile-time
                fma2(ac0[n], t[c], w0);
                fma2(ac1[n], t[c], w1);
                fma2(ac2[n], t[c], w2);
                fma2(ac3[n], t[c], w3);
            }
        }
        __syncwarp();

        // ---- relu + transposed h store: rows 2l, 2l+1 hold h[4l..4l+3] ----
        {
            const int r0 = 2 * lane, r1 = 2 * lane + 1;
            const int s0 = (r0 >> 2) & 7, s1 = (r1 >> 2) & 7;
#pragma unroll
            for (int n = 0; n < 8; n++) {
                float2 p0 = unpack2(ac0[n]);
                float2 p1 = unpack2(ac1[n]);
                float2 p2 = unpack2(ac2[n]);
                float2 p3 = unpack2(ac3[n]);
                float h0 = fmaxf(p0.x + p0.y, 0.f);
                float h1 = fmaxf(p1.x + p1.y, 0.f);
                float h2 = fmaxf(p2.x + p2.y, 0.f);
                float h3 = fmaxf(p3.x + p3.y, 0.f);
                sts64(bufA + r0 * 80 + (((n ^ s0) & 7) << 3), pack2(h0, h1));
                sts64(bufA + r1 * 80 + (((n ^ s1) & 7) << 3), pack2(h2, h3));
            }
        }
        __syncwarp();

        // ---- layer 2: 64 outputs, lane owns o = 2l, 2l+1 ----
        u64 aA[8], aB[8];
#pragma unroll
        for (int n = 0; n < 8; n++) {
            aA[n] = pack2(b2v.x, 0.f);
            aB[n] = pack2(b2v.y, 0.f);
        }
        for (int kk0 = 0; kk0 < 64; kk0 += 32) {
#pragma unroll
            for (int u = 0; u < 32; u++) {
                const int kk = kk0 + u;
                const int s = (u >> 2) & 7;  // kk0>>2 in {0,8} == 0 mod 8
                u64 w0, w1;
                lds64v2(w0, w1, w2A + kk * 512 + lane * 16);
                u64 t[8];
                unsigned rb = bufA + kk * 80;
                lds64v2(t[0], t[1], rb);
                lds64v2(t[2], t[3], rb + 16);
                lds64v2(t[4], t[5], rb + 32);
                lds64v2(t[6], t[7], rb + 48);
#pragma unroll
                for (int c = 0; c < 8; c++) {
                    const int n = c ^ s;
                    fma2(aA[n], t[c], w0);
                    fma2(aB[n], t[c], w1);
                }
            }
        }

        // ---- epilogue: coalesced float2 stores ----
#pragma unroll
        for (int n = 0; n < 8; n++) {
            float2 pa = unpack2(aA[n]);
            float2 pb = unpack2(aB[n]);
            float2 y = make_float2(pa.x + pa.y, pb.x + pb.y);
            reinterpret_cast<float2*>(out)[(base + n) * 32 + lane] = y;
        }
        __syncwarp();  // buf reads done before next iter's act stores
    }
}

// ---------------------------------------------------------------------------
extern "C" void kernel_launch(void* const* d_in, const int* in_sizes, int n_in,
                              void* d_out, int out_size) {
    const float* x = (const float*)d_in[0];
    const int* ei32 = (const int*)d_in[1];
    const float* W1 = (const float*)d_in[2];
    const float* b1 = (const float*)d_in[3];
    const float* W2 = (const float*)d_in[4];
    const float* b2 = (const float*)d_in[5];
    float* out = (float*)d_out;

    // 0) detect edge_index dtype (int32 vs int64)
    detect_dtype_kernel<<<1, 32>>>(ei32);

    // 1) zero agg
    {
        int n = N_NODES * D / 4;
        zero_agg_kernel<<<(n + 255) / 256, 256>>>();
    }
    // 2) scatter-add over edges
    {
        long long total = (long long)N_EDGES * 16;
        int blocks = (int)((total + 255) / 256);
        scatter_kernel<<<blocks, 256>>>((const float4*)x, ei32);
    }
    // 3) fused MLP (adds the (1+eps)*x term itself)
    {
        const int smemBytes = 106496;
        cudaFuncSetAttribute(mlp_kernel,
                             cudaFuncAttributeMaxDynamicSharedMemorySize,
                             smemBytes);
        mlp_kernel<<<296, 256, smemBytes>>>(x, W1, b1, W2, b2, out);
    }
}